// round 8
// baseline (speedup 1.0000x reference)
#include <cuda_runtime.h>
#include <cuda_bf16.h>
#include <cstdint>

// RoPE2D encoder: output = [cos_2d (HW x 128) ; sin_2d (HW x 128)], fp32.
// H = W = 512, DIM = 128. Channels [0,64) depend only on x, [64,128) only on y.
// Single fused kernel. Lane computes its 4 channel values analytically:
// sincosf for the initial angle, then an angle-addition rotation across the
// 16 rows this warp writes (x-lanes rotate by f, y-lanes by 0 = identity).
// 16 rows/warp halves trig cost per byte vs the 8-row version.

#define RP_H 512
#define RP_W 512
#define RP_HW (RP_H * RP_W)
#define ROWS_PER_WARP 16

// Warp: fixed `which` (cos/sin), 16 consecutive positions p0..p0+15 (same y,
// since 16 | 512). Lane q = float4 chunk (4 channels) of the 128-channel row.
//   q<16 : x-half, channels 4q..4q+3, freq index 4*(q&7)+j, angle (x0+i)*f
//   q>=16: y-half, channels 64+4(q-16).., freq index 4*(q&7)+j, angle y*f
__global__ void __launch_bounds__(256) rope2d_fused(float4* __restrict__ out,
                                                    const float* __restrict__ inv_freq_x,
                                                    const float* __restrict__ inv_freq_y) {
    unsigned warp_in_block = threadIdx.x >> 5;
    unsigned q             = threadIdx.x & 31u;
    unsigned gw    = blockIdx.x * 8u + warp_in_block;   // 0..32767
    unsigned which = gw >> 14;                          // 0 = cos, 1 = sin
    unsigned rp    = gw & 16383u;
    unsigned p0    = rp * ROWS_PER_WARP;
    unsigned y     = p0 >> 9;
    unsigned x0    = p0 & 511u;

    bool is_x = (q < 16u);

    const float4* tf = reinterpret_cast<const float4*>(is_x ? inv_freq_x : inv_freq_y);
    float4 f4 = __ldg(tf + (q & 7u));
    float fr[4] = {f4.x, f4.y, f4.z, f4.w};

    float pos  = is_x ? (float)x0 : (float)y;
    float step = is_x ? 1.0f : 0.0f;          // y-lanes: identity rotation

    float c[4], s[4], cf[4], sf[4];
    #pragma unroll
    for (int j = 0; j < 4; j++) {
        sincosf(pos * fr[j], &s[j], &c[j]);
        sincosf(step * fr[j], &sf[j], &cf[j]);
    }

    float4* row = out + (size_t)which * (RP_HW * 32u) + (size_t)p0 * 32u + q;

    #pragma unroll
    for (int i = 0; i < ROWS_PER_WARP; i++) {
        float4 val;
        val.x = which ? s[0] : c[0];
        val.y = which ? s[1] : c[1];
        val.z = which ? s[2] : c[2];
        val.w = which ? s[3] : c[3];
        __stcs(row + (size_t)i * 32u, val);    // streaming store, 512B/warp

        if (i < ROWS_PER_WARP - 1) {
            #pragma unroll
            for (int j = 0; j < 4; j++) {
                float cn = fmaf(c[j], cf[j], -s[j] * sf[j]);
                float sn = fmaf(s[j], cf[j],  c[j] * sf[j]);
                c[j] = cn;
                s[j] = sn;
            }
        }
    }
}

extern "C" void kernel_launch(void* const* d_in, const int* in_sizes, int n_in,
                              void* d_out, int out_size) {
    const float* inv_freq_x = (const float*)d_in[1];
    const float* inv_freq_y = (const float*)d_in[2];
    float4* out = (float4*)d_out;

    // 32768 warps = 2 (which) x 16384 row-groups; 8 warps/block -> 4096 blocks
    rope2d_fused<<<4096, 256>>>(out, inv_freq_x, inv_freq_y);
}